// round 6
// baseline (speedup 1.0000x reference)
#include <cuda_runtime.h>
#include <cuda_bf16.h>
#include <cstdint>

// ---------------- problem constants ----------------
#define L_SEQ    2048
#define D_MODEL  1024
#define D_INNER  2048
#define D_XB     512
#define D_STATE  16
#define DT_RANK  64
#define KCONV    4
#define G_HEADS  128
#define GX_HEADS 32
#define D_PROJ   5184
#define NPAD1    5248          // D_PROJ padded to multiple of 128

#define OFF_Z    0
#define OFF_X    2048
#define OFF_B    2560
#define OFF_C    3072
#define OFF_DT   5120

// scan chunking
#define CH       64
#define NCH      32            // L_SEQ / CH

// ---------------- scratch (static device globals; no runtime allocation) ----
__device__ float g_zx   [L_SEQ * D_PROJ];
__device__ float g_delta[L_SEQ * D_INNER];
__device__ float g_xconv[L_SEQ * D_XB];

__device__ float g_P  [NCH * G_HEADS * 256];
__device__ float g_E  [NCH * G_HEADS * 256];
__device__ float g_Cin[NCH * G_HEADS * 256];

__device__ __nv_bfloat16 g_ahi [L_SEQ * D_INNER];
__device__ __nv_bfloat16 g_alo [L_SEQ * D_INNER];
__device__ __nv_bfloat16 g_w1hi[NPAD1 * D_MODEL];
__device__ __nv_bfloat16 g_w1lo[NPAD1 * D_MODEL];
__device__ __nv_bfloat16 g_w2hi[D_MODEL * D_INNER];
__device__ __nv_bfloat16 g_w2lo[D_MODEL * D_INNER];

// ================= low-level helpers =========================================
__device__ __forceinline__ uint32_t smem_u32(const void* p) {
    return (uint32_t)__cvta_generic_to_shared(p);
}
__device__ __forceinline__ void cpasync16(uint32_t saddr, const void* g) {
    asm volatile("cp.async.cg.shared.global [%0], [%1], 16;" :: "r"(saddr), "l"(g));
}
__device__ __forceinline__ void ldsm4(uint32_t* r, uint32_t addr) {
    asm volatile("ldmatrix.sync.aligned.m8n8.x4.shared.b16 {%0,%1,%2,%3}, [%4];"
        : "=r"(r[0]), "=r"(r[1]), "=r"(r[2]), "=r"(r[3]) : "r"(addr));
}
__device__ __forceinline__ void mma16816(float* d, const uint32_t* a, const uint32_t* b) {
    asm volatile("mma.sync.aligned.m16n8k16.row.col.f32.bf16.bf16.f32 "
        "{%0,%1,%2,%3}, {%4,%5,%6,%7}, {%8,%9}, {%0,%1,%2,%3};"
        : "+f"(d[0]), "+f"(d[1]), "+f"(d[2]), "+f"(d[3])
        : "r"(a[0]), "r"(a[1]), "r"(a[2]), "r"(a[3]), "r"(b[0]), "r"(b[1]));
}
__device__ __forceinline__ uint32_t sw32(uint32_t off) {
    return off ^ ((off >> 3) & 0x70);
}

// ================= fp32 -> bf16 hi/lo conversion =============================
__global__ void __launch_bounds__(256)
convert_hilo(const float* __restrict__ in, __nv_bfloat16* __restrict__ hi,
             __nv_bfloat16* __restrict__ lo, int count)
{
    int i = (blockIdx.x * 256 + threadIdx.x) * 4;
    if (i >= count) return;
    float4 v = *(const float4*)(in + i);
    float vv[4] = {v.x, v.y, v.z, v.w};
    __nv_bfloat16 h[4], l[4];
    #pragma unroll
    for (int j = 0; j < 4; ++j) {
        h[j] = __float2bfloat16_rn(vv[j]);
        l[j] = __float2bfloat16_rn(vv[j] - __bfloat162float(h[j]));
    }
    *(uint2*)(hi + i) = *(uint2*)h;
    *(uint2*)(lo + i) = *(uint2*)l;
}

// ================= transpose W [K,N] -> [Npad,K] bf16 hi/lo ==================
__global__ void __launch_bounds__(256)
transpose_wt(const float* __restrict__ W, __nv_bfloat16* __restrict__ Thi,
             __nv_bfloat16* __restrict__ Tlo, int K, int N)
{
    __shared__ float tile[32][33];
    int n0 = blockIdx.x * 32;
    int k0 = blockIdx.y * 32;
    int tx = threadIdx.x & 31, ty = threadIdx.x >> 5;
    #pragma unroll
    for (int r = 0; r < 4; ++r) {
        int k = k0 + ty + r * 8;
        int n = n0 + tx;
        tile[ty + r * 8][tx] = (n < N) ? W[(size_t)k * N + n] : 0.f;
    }
    __syncthreads();
    #pragma unroll
    for (int r = 0; r < 4; ++r) {
        int n = n0 + ty + r * 8;
        int k = k0 + tx;
        float v = tile[tx][ty + r * 8];
        __nv_bfloat16 h = __float2bfloat16_rn(v);
        Thi[(size_t)n * K + k] = h;
        Tlo[(size_t)n * K + k] = __float2bfloat16_rn(v - __bfloat162float(h));
    }
}

// ================= split-bf16 warp-MMA GEMM (persistent tiles) ===============
// Tile: 128 x (NF*32). 8 warps (2m x 4n), warp tile 64 x (NF*8).
// 4-stage cp.async pipeline with exact tail waits.
#define KTILE    16
#define NSTAGE   4

template<int NF>
__global__ void __launch_bounds__(256, 2)
gemm_tc_kernel(const __nv_bfloat16* __restrict__ Ahi, const __nv_bfloat16* __restrict__ Alo,
               const __nv_bfloat16* __restrict__ Bhi, const __nv_bfloat16* __restrict__ Blo,
               float* __restrict__ C, int Nreal, int K, int tilesX, int ntiles)
{
    constexpr int NT  = NF * 32;               // B rows per tile
    constexpr int SB  = 8192 + NT * 64;        // stage bytes
    constexpr int CPT = 2 + NT / 64;           // 16B chunks per thread per stage

    extern __shared__ char sm[];
    const uint32_t sb = smem_u32(sm);
    const int tid   = threadIdx.x;
    const int lane  = tid & 31;
    const int wid   = tid >> 5;
    const int wmB   = (wid >> 2) * 64;
    const int wnB   = (wid & 3) * (NF * 8);
    const int nkt   = K / KTILE;

    // per-thread chunk table (tile-independent smem offsets)
    int crow[CPT], cch[CPT], carr[CPT];
    uint32_t csm[CPT];
    #pragma unroll
    for (int i = 0; i < CPT; ++i) {
        int idx = tid + i * 256;
        if (idx < 512) {                       // A-hi / A-lo
            carr[i] = idx >> 8;                // 0,1
            int w = idx & 255;
            crow[i] = w >> 1; cch[i] = w & 1;
            csm[i]  = (uint32_t)carr[i] * 4096u
                    + sw32((uint32_t)crow[i] * 32u + (uint32_t)cch[i] * 16u);
        } else {                               // B-hi / B-lo
            int rem = idx - 512;
            int bl  = (rem >= 2 * NT) ? 1 : 0;
            carr[i] = 2 + bl;
            int w = rem & (2 * NT - 1);
            crow[i] = w >> 1; cch[i] = w & 1;
            csm[i]  = 8192u + (uint32_t)bl * (NT * 32u)
                    + sw32((uint32_t)crow[i] * 32u + (uint32_t)cch[i] * 16u);
        }
    }

    const uint32_t a_row = (uint32_t)(wmB + (lane & 15));
    const uint32_t a_cb  = (uint32_t)((lane >> 4) * 16);
    const uint32_t b_row = (uint32_t)(wnB + ((lane >> 4) & 1) * 8 + (lane & 7));
    const uint32_t b_cb  = (uint32_t)(((lane >> 3) & 1) * 16);

    for (int tile = blockIdx.x; tile < ntiles; tile += gridDim.x) {
        const int nBase = (tile % tilesX) * NT;
        const int mBase = (tile / tilesX) * 128;

        float acc[4][NF][4];
        #pragma unroll
        for (int a = 0; a < 4; ++a)
            #pragma unroll
            for (int b = 0; b < NF; ++b)
                #pragma unroll
                for (int c = 0; c < 4; ++c) acc[a][b][c] = 0.f;

        auto load_stage = [&](int stg, int kt) {
            const size_t koff = (size_t)kt * KTILE;
            uint32_t base = sb + (uint32_t)stg * SB;
            #pragma unroll
            for (int i = 0; i < CPT; ++i) {
                const __nv_bfloat16* src;
                size_t goff;
                if (carr[i] < 2) {
                    src  = (carr[i] == 0) ? Ahi : Alo;
                    goff = (size_t)(mBase + crow[i]) * K + koff + (size_t)cch[i] * 8;
                } else {
                    src  = (carr[i] == 2) ? Bhi : Blo;
                    goff = (size_t)(nBase + crow[i]) * K + koff + (size_t)cch[i] * 8;
                }
                cpasync16(base + csm[i], src + goff);
            }
            asm volatile("cp.async.commit_group;" ::: "memory");
        };

        load_stage(0, 0);
        load_stage(1, 1);
        load_stage(2, 2);

        for (int kt = 0; kt < nkt; ++kt) {
            // exact tail waits: guarantee ktile kt's group is complete
            if (kt < nkt - 2)       asm volatile("cp.async.wait_group 2;" ::: "memory");
            else if (kt == nkt - 2) asm volatile("cp.async.wait_group 1;" ::: "memory");
            else                    asm volatile("cp.async.wait_group 0;" ::: "memory");
            __syncthreads();

            const uint32_t stg  = sb + (uint32_t)(kt % NSTAGE) * SB;
            const uint32_t sAhi = stg;
            const uint32_t sAlo = stg + 4096;
            const uint32_t sBhi = stg + 8192;
            const uint32_t sBlo = stg + 8192 + NT * 32;

            uint32_t bh[NF][2], bl[NF][2];
            #pragma unroll
            for (int nf2 = 0; nf2 < NF / 2; ++nf2) {
                uint32_t off = sw32((b_row + (uint32_t)nf2 * 16u) * 32u + b_cb);
                uint32_t r[4];
                ldsm4(r, sBhi + off);
                bh[nf2*2][0] = r[0]; bh[nf2*2][1] = r[1];
                bh[nf2*2+1][0] = r[2]; bh[nf2*2+1][1] = r[3];
                ldsm4(r, sBlo + off);
                bl[nf2*2][0] = r[0]; bl[nf2*2][1] = r[1];
                bl[nf2*2+1][0] = r[2]; bl[nf2*2+1][1] = r[3];
            }

            #pragma unroll
            for (int mf = 0; mf < 4; ++mf) {
                uint32_t off = sw32((a_row + (uint32_t)mf * 16u) * 32u + a_cb);
                uint32_t ah[4], al[4];
                ldsm4(ah, sAhi + off);
                ldsm4(al, sAlo + off);
                #pragma unroll
                for (int nf = 0; nf < NF; ++nf) {
                    mma16816(acc[mf][nf], ah, bh[nf]);
                    mma16816(acc[mf][nf], ah, bl[nf]);
                    mma16816(acc[mf][nf], al, bh[nf]);
                }
            }
            if (kt + 3 < nkt) load_stage((kt + 3) % NSTAGE, kt + 3);
        }

        const int gid = lane >> 2;
        const int tig = lane & 3;
        #pragma unroll
        for (int mf = 0; mf < 4; ++mf) {
            int row0 = mBase + wmB + mf * 16 + gid;
            #pragma unroll
            for (int nf = 0; nf < NF; ++nf) {
                int col = nBase + wnB + nf * 8 + tig * 2;
                if (col < Nreal) {
                    float2 v0 = make_float2(acc[mf][nf][0], acc[mf][nf][1]);
                    float2 v1 = make_float2(acc[mf][nf][2], acc[mf][nf][3]);
                    *(float2*)(C + (size_t)row0 * Nreal + col) = v0;
                    *(float2*)(C + (size_t)(row0 + 8) * Nreal + col) = v1;
                }
            }
        }
        __syncthreads();   // protect smem before next tile's prologue
    }
}

// ---------------- dt projection + softplus ------------------------------------
__global__ void __launch_bounds__(256)
dt_kernel(const float* __restrict__ W_dt, const float* __restrict__ dt_bias)
{
    __shared__ float s_r[64 * DT_RANK];
    const int t0 = blockIdx.x * 64;
    const int d  = blockIdx.y * 256 + threadIdx.x;

    #pragma unroll
    for (int k = 0; k < 16; ++k) {
        int idx = threadIdx.x + k * 256;
        int row = idx >> 6, col = idx & 63;
        s_r[idx] = g_zx[(size_t)(t0 + row) * D_PROJ + OFF_DT + col];
    }
    __syncthreads();

    float w[DT_RANK];
    #pragma unroll
    for (int k = 0; k < DT_RANK; ++k)
        w[k] = W_dt[(size_t)k * D_INNER + d];

    const float bias2 = 2.f * dt_bias[d];

    for (int tt = 0; tt < 64; ++tt) {
        const float4* rp = (const float4*)(s_r + tt * DT_RANK);
        float s = bias2;
        #pragma unroll
        for (int k4 = 0; k4 < DT_RANK / 4; ++k4) {
            float4 r4 = rp[k4];
            s = fmaf(r4.x, w[k4*4+0], s);
            s = fmaf(r4.y, w[k4*4+1], s);
            s = fmaf(r4.z, w[k4*4+2], s);
            s = fmaf(r4.w, w[k4*4+3], s);
        }
        float sp = (s > 20.f) ? s : log1pf(__expf(s));
        g_delta[(size_t)(t0 + tt) * D_INNER + d] = sp;
    }
}

// ---------------- causal depthwise conv (K=4) + bias + silu -----------------
__global__ void __launch_bounds__(256)
conv_kernel(const float* __restrict__ w, const float* __restrict__ b)
{
    int idx = blockIdx.x * blockDim.x + threadIdx.x;
    if (idx >= L_SEQ * D_XB) return;
    int t = idx >> 9, c = idx & (D_XB - 1);
    float acc = b[c];
    #pragma unroll
    for (int k = 0; k < KCONV; ++k) {
        int tt = t - (KCONV - 1) + k;
        if (tt >= 0)
            acc = fmaf(w[c * KCONV + k], g_zx[(size_t)tt * D_PROJ + OFF_X + c], acc);
    }
    g_xconv[idx] = acc / (1.f + __expf(-acc));
}

// ---------------- chunked selective scan -------------------------------------
__global__ void __launch_bounds__(256)
scan_phase_a(const float* __restrict__ A_log)
{
    const int g   = blockIdx.x;
    const int j   = blockIdx.y;
    const int tid = threadIdx.x;
    const int p   = tid >> 4;
    const int n   = tid & 15;
    const int gx  = g >> 2;
    const int d   = g * D_STATE + p;

    __shared__ float s_dv[CH * 16], s_xv[CH * 16], s_B[CH * 16];

    const int i0 = tid >> 4, l = tid & 15;
    const int tbase = j * CH;
    #pragma unroll
    for (int r = 0; r < CH; r += 16) {
        int t = tbase + i0 + r;
        s_dv[(i0 + r) * 16 + l] = g_delta[(size_t)t * D_INNER + g * 16 + l];
        s_xv[(i0 + r) * 16 + l] = g_xconv[(size_t)t * D_XB + gx * 16 + l];
        s_B [(i0 + r) * 16 + l] = g_zx[(size_t)t * D_PROJ + OFF_B + gx * 16 + l];
    }
    __syncthreads();

    const float A = -expf(A_log[d * D_STATE + n]);
    float h = 0.f, P = 1.f;
    #pragma unroll 8
    for (int i = 0; i < CH; ++i) {
        float dv = s_dv[i * 16 + p];
        float xv = s_xv[i * 16 + p];
        float Bv = s_B [i * 16 + n];
        float a  = __expf(dv * A);
        P *= a;
        h = fmaf(a, h, dv * xv * Bv);
    }
    int idx = (j * G_HEADS + g) * 256 + tid;
    g_P[idx] = P;
    g_E[idx] = h;
}

__global__ void __launch_bounds__(256)
scan_phase_b()
{
    const int g   = blockIdx.x;
    const int tid = threadIdx.x;
    float c = 0.f;
    #pragma unroll
    for (int j = 0; j < NCH; ++j) {
        int idx = (j * G_HEADS + g) * 256 + tid;
        float P = g_P[idx];
        float E = g_E[idx];
        g_Cin[idx] = c;
        c = fmaf(P, c, E);
    }
}

__global__ void __launch_bounds__(256)
scan_phase_c(const float* __restrict__ A_log, const float* __restrict__ Dp)
{
    const int g   = blockIdx.x;
    const int j   = blockIdx.y;
    const int tid = threadIdx.x;
    const int p   = tid >> 4;
    const int n   = tid & 15;
    const int gx  = g >> 2;
    const int d   = g * D_STATE + p;

    __shared__ float s_dv[CH * 16], s_xv[CH * 16], s_B[CH * 16],
                     s_C [CH * 16], s_z [CH * 16];

    const int i0 = tid >> 4, l = tid & 15;
    const int tbase = j * CH;
    #pragma unroll
    for (int r = 0; r < CH; r += 16) {
        int t = tbase + i0 + r;
        s_dv[(i0 + r) * 16 + l] = g_delta[(size_t)t * D_INNER + g * 16 + l];
        s_xv[(i0 + r) * 16 + l] = g_xconv[(size_t)t * D_XB + gx * 16 + l];
        s_B [(i0 + r) * 16 + l] = g_zx[(size_t)t * D_PROJ + OFF_B + gx * 16 + l];
        s_C [(i0 + r) * 16 + l] = g_zx[(size_t)t * D_PROJ + OFF_C + g * 16 + l];
        s_z [(i0 + r) * 16 + l] = g_zx[(size_t)t * D_PROJ + OFF_Z + g * 16 + l];
    }
    __syncthreads();

    const float A  = -expf(A_log[d * D_STATE + n]);
    const float Dv = Dp[d];
    float h = g_Cin[(j * G_HEADS + g) * 256 + tid];

    #pragma unroll 4
    for (int i = 0; i < CH; ++i) {
        float dv = s_dv[i * 16 + p];
        float xv = s_xv[i * 16 + p];
        float Bv = s_B [i * 16 + n];
        float Cv = s_C [i * 16 + n];

        float a = __expf(dv * A);
        h = fmaf(a, h, dv * xv * Bv);

        float part = h * Cv;
        part += __shfl_xor_sync(0xffffffffu, part, 8);
        part += __shfl_xor_sync(0xffffffffu, part, 4);
        part += __shfl_xor_sync(0xffffffffu, part, 2);
        part += __shfl_xor_sync(0xffffffffu, part, 1);

        if (n == 0) {
            float zv = s_z[i * 16 + p];
            float sz = zv / (1.f + __expf(-zv));
            float yv = (part + Dv * xv) * sz;
            size_t oi = (size_t)(tbase + i) * D_INNER + d;
            __nv_bfloat16 hb = __float2bfloat16_rn(yv);
            g_ahi[oi] = hb;
            g_alo[oi] = __float2bfloat16_rn(yv - __bfloat162float(hb));
        }
    }
}

// ---------------- launch ------------------------------------------------------
extern "C" void kernel_launch(void* const* d_in, const int* in_sizes, int n_in,
                              void* d_out, int out_size)
{
    const float* hidden  = (const float*)d_in[0];
    const float* W_in    = (const float*)d_in[1];
    const float* conv_w  = (const float*)d_in[2];
    const float* conv_b  = (const float*)d_in[3];
    const float* W_dt    = (const float*)d_in[4];
    const float* dt_bias = (const float*)d_in[5];
    const float* A_log   = (const float*)d_in[6];
    const float* Dp      = (const float*)d_in[7];
    const float* W_out   = (const float*)d_in[8];
    float*       out     = (float*)d_out;

    const int SMEM1 = NSTAGE * (8192 + 128 * 64);   // 64KB  (NF=4)
    const int SMEM2 = NSTAGE * (8192 + 64 * 64);    // 48KB  (NF=2)
    cudaFuncSetAttribute(gemm_tc_kernel<4>,
                         cudaFuncAttributeMaxDynamicSharedMemorySize, SMEM1);
    cudaFuncSetAttribute(gemm_tc_kernel<2>,
                         cudaFuncAttributeMaxDynamicSharedMemorySize, SMEM2);

    float* zx;
    __nv_bfloat16 *ahi, *alo, *w1hi, *w1lo, *w2hi, *w2lo;
    cudaGetSymbolAddress((void**)&zx,   g_zx);
    cudaGetSymbolAddress((void**)&ahi,  g_ahi);
    cudaGetSymbolAddress((void**)&alo,  g_alo);
    cudaGetSymbolAddress((void**)&w1hi, g_w1hi);
    cudaGetSymbolAddress((void**)&w1lo, g_w1lo);
    cudaGetSymbolAddress((void**)&w2hi, g_w2hi);
    cudaGetSymbolAddress((void**)&w2lo, g_w2lo);

    // 1-3) operand prep (GEMM1 lands in profiled slot 4)
    transpose_wt<<<dim3(NPAD1 / 32, D_MODEL / 32), 256>>>(W_in, w1hi, w1lo, D_MODEL, D_PROJ);
    transpose_wt<<<dim3(D_MODEL / 32, D_INNER / 32), 256>>>(W_out, w2hi, w2lo, D_INNER, D_MODEL);
    convert_hilo<<<(L_SEQ * D_MODEL) / 1024, 256>>>(hidden, ahi, alo, L_SEQ * D_MODEL);

    // 4) zxbcdt = hidden @ W_in  — persistent tiles, grid = 2 * 148
    {
        int tilesX = NPAD1 / 128, ntiles = tilesX * (L_SEQ / 128);   // 41*16 = 656
        gemm_tc_kernel<4><<<296, 256, SMEM1>>>(
            ahi, alo, w1hi, w1lo, zx, D_PROJ, D_MODEL, tilesX, ntiles);
    }

    // 5-6) delta + conv
    dt_kernel<<<dim3(L_SEQ / 64, D_INNER / 256), 256>>>(W_dt, dt_bias);
    conv_kernel<<<(L_SEQ * D_XB + 255) / 256, 256>>>(conv_w, conv_b);

    // 7-9) chunked scan (phase C writes bf16 hi/lo yg into g_ahi/g_alo)
    scan_phase_a<<<dim3(G_HEADS, NCH), 256>>>(A_log);
    scan_phase_b<<<G_HEADS, 256>>>();
    scan_phase_c<<<dim3(G_HEADS, NCH), 256>>>(A_log, Dp);

    // 10) out = yg @ W_out  — 128x64 tiles, 256 CTAs fill all SMs
    {
        int tilesX = D_MODEL / 64, ntiles = tilesX * (L_SEQ / 128);  // 16*16 = 256
        gemm_tc_kernel<2><<<256, 256, SMEM2>>>(
            ahi, alo, w2hi, w2lo, out, D_MODEL, D_INNER, tilesX, ntiles);
    }
}

// round 7
// speedup vs baseline: 1.0321x; 1.0321x over previous
#include <cuda_runtime.h>
#include <cuda_bf16.h>
#include <cstdint>

// ---------------- problem constants ----------------
#define L_SEQ    2048
#define D_MODEL  1024
#define D_INNER  2048
#define D_XB     512
#define D_STATE  16
#define DT_RANK  64
#define KCONV    4
#define G_HEADS  128
#define GX_HEADS 32
#define D_PROJ   5184
#define NPAD1    5248          // D_PROJ padded to multiple of 128

#define OFF_Z    0
#define OFF_X    2048
#define OFF_B    2560
#define OFF_C    3072
#define OFF_DT   5120

// scan chunking
#define CH       64
#define NCH      32            // L_SEQ / CH

// ---------------- scratch (static device globals; no runtime allocation) ----
__device__ float g_zx   [L_SEQ * D_PROJ];
__device__ float g_delta[L_SEQ * D_INNER];
__device__ float g_xconv[L_SEQ * D_XB];

__device__ float g_P  [NCH * G_HEADS * 256];
__device__ float g_E  [NCH * G_HEADS * 256];
__device__ float g_Cin[NCH * G_HEADS * 256];

__device__ __nv_bfloat16 g_ahi [L_SEQ * D_INNER];
__device__ __nv_bfloat16 g_alo [L_SEQ * D_INNER];
__device__ __nv_bfloat16 g_w1hi[NPAD1 * D_MODEL];
__device__ __nv_bfloat16 g_w1lo[NPAD1 * D_MODEL];
__device__ __nv_bfloat16 g_w2hi[D_MODEL * D_INNER];
__device__ __nv_bfloat16 g_w2lo[D_MODEL * D_INNER];

// ================= low-level helpers =========================================
__device__ __forceinline__ uint32_t smem_u32(const void* p) {
    return (uint32_t)__cvta_generic_to_shared(p);
}
__device__ __forceinline__ void cpasync16(uint32_t saddr, const void* g) {
    asm volatile("cp.async.cg.shared.global [%0], [%1], 16;" :: "r"(saddr), "l"(g));
}
__device__ __forceinline__ void ldsm4(uint32_t* r, uint32_t addr) {
    asm volatile("ldmatrix.sync.aligned.m8n8.x4.shared.b16 {%0,%1,%2,%3}, [%4];"
        : "=r"(r[0]), "=r"(r[1]), "=r"(r[2]), "=r"(r[3]) : "r"(addr));
}
__device__ __forceinline__ void mma16816(float* d, const uint32_t* a, const uint32_t* b) {
    asm volatile("mma.sync.aligned.m16n8k16.row.col.f32.bf16.bf16.f32 "
        "{%0,%1,%2,%3}, {%4,%5,%6,%7}, {%8,%9}, {%0,%1,%2,%3};"
        : "+f"(d[0]), "+f"(d[1]), "+f"(d[2]), "+f"(d[3])
        : "r"(a[0]), "r"(a[1]), "r"(a[2]), "r"(a[3]), "r"(b[0]), "r"(b[1]));
}
__device__ __forceinline__ uint32_t sw32(uint32_t off) {
    return off ^ ((off >> 3) & 0x70);
}

// ================= fp32 -> bf16 hi/lo conversion =============================
__global__ void __launch_bounds__(256)
convert_hilo(const float* __restrict__ in, __nv_bfloat16* __restrict__ hi,
             __nv_bfloat16* __restrict__ lo, int count)
{
    int i = (blockIdx.x * 256 + threadIdx.x) * 4;
    if (i >= count) return;
    float4 v = *(const float4*)(in + i);
    float vv[4] = {v.x, v.y, v.z, v.w};
    __nv_bfloat16 h[4], l[4];
    #pragma unroll
    for (int j = 0; j < 4; ++j) {
        h[j] = __float2bfloat16_rn(vv[j]);
        l[j] = __float2bfloat16_rn(vv[j] - __bfloat162float(h[j]));
    }
    *(uint2*)(hi + i) = *(uint2*)h;
    *(uint2*)(lo + i) = *(uint2*)l;
}

// ================= transpose W [K,N] -> [Npad,K] bf16 hi/lo ==================
__global__ void __launch_bounds__(256)
transpose_wt(const float* __restrict__ W, __nv_bfloat16* __restrict__ Thi,
             __nv_bfloat16* __restrict__ Tlo, int K, int N)
{
    __shared__ float tile[32][33];
    int n0 = blockIdx.x * 32;
    int k0 = blockIdx.y * 32;
    int tx = threadIdx.x & 31, ty = threadIdx.x >> 5;
    #pragma unroll
    for (int r = 0; r < 4; ++r) {
        int k = k0 + ty + r * 8;
        int n = n0 + tx;
        tile[ty + r * 8][tx] = (n < N) ? W[(size_t)k * N + n] : 0.f;
    }
    __syncthreads();
    #pragma unroll
    for (int r = 0; r < 4; ++r) {
        int n = n0 + ty + r * 8;
        int k = k0 + tx;
        float v = tile[tx][ty + r * 8];
        __nv_bfloat16 h = __float2bfloat16_rn(v);
        Thi[(size_t)n * K + k] = h;
        Tlo[(size_t)n * K + k] = __float2bfloat16_rn(v - __bfloat162float(h));
    }
}

// ================= split-bf16 warp-MMA GEMM ==================================
// CTA tile 128x128, 8 warps (2m x 4n), warp tile 64x32.
// Pipeline stage = TWO k=16 slices (32KB). 3 stages, one barrier per stage.
#define SLICE_B  16384          // one k=16 slice: 4 arrays x 4KB
#define STAGE_B  (2 * SLICE_B)  // 32KB
#define NSTAGE   3
#define GEMM_SMEM (NSTAGE * STAGE_B)   // 96KB

__global__ void __launch_bounds__(256, 2)
gemm_tc_kernel(const __nv_bfloat16* __restrict__ Ahi, const __nv_bfloat16* __restrict__ Alo,
               const __nv_bfloat16* __restrict__ Bhi, const __nv_bfloat16* __restrict__ Blo,
               float* __restrict__ C, int Nreal, int K)
{
    extern __shared__ char sm[];
    const uint32_t sb = smem_u32(sm);
    const int tid   = threadIdx.x;
    const int lane  = tid & 31;
    const int wid   = tid >> 5;
    const int nBase = blockIdx.x * 128;
    const int mBase = blockIdx.y * 128;
    const int wmB   = (wid >> 2) * 64;
    const int wnB   = (wid & 3) * 32;

    const int nst = K >> 5;               // stages of k=32

    float acc[4][4][4];
    #pragma unroll
    for (int a = 0; a < 4; ++a)
        #pragma unroll
        for (int b = 0; b < 4; ++b)
            #pragma unroll
            for (int c = 0; c < 4; ++c) acc[a][b][c] = 0.f;

    // per-thread load table for ONE slice (4 x 16B chunks); reused for both slices
    int lrow[4], lch[4], larr[4];
    uint32_t lsw[4];
    #pragma unroll
    for (int i = 0; i < 4; ++i) {
        int idx = tid + i * 256;
        larr[i] = idx >> 8;
        int w = idx & 255;
        lrow[i] = w >> 1;
        lch[i]  = w & 1;
        lsw[i]  = (uint32_t)larr[i] * 4096u
                + sw32((uint32_t)lrow[i] * 32u + (uint32_t)lch[i] * 16u);
    }

    auto load_stage = [&](int stg, int s) {
        uint32_t base = sb + (uint32_t)stg * STAGE_B;
        #pragma unroll
        for (int q = 0; q < 2; ++q) {
            const size_t koff = (size_t)s * 32 + (size_t)q * 16;
            uint32_t sbase = base + (uint32_t)q * SLICE_B;
            #pragma unroll
            for (int i = 0; i < 4; ++i) {
                const __nv_bfloat16* src;
                size_t goff;
                if (larr[i] < 2) {
                    src  = (larr[i] == 0) ? Ahi : Alo;
                    goff = (size_t)(mBase + lrow[i]) * K + koff + (size_t)lch[i] * 8;
                } else {
                    src  = (larr[i] == 2) ? Bhi : Blo;
                    goff = (size_t)(nBase + lrow[i]) * K + koff + (size_t)lch[i] * 8;
                }
                cpasync16(sbase + lsw[i], src + goff);
            }
        }
        asm volatile("cp.async.commit_group;" ::: "memory");
    };

    // prologue: 2 stages in flight
    load_stage(0, 0);
    load_stage(1, 1);

    const uint32_t a_row = (uint32_t)(wmB + (lane & 15));
    const uint32_t a_cb  = (uint32_t)((lane >> 4) * 16);
    const uint32_t b_row = (uint32_t)(wnB + ((lane >> 4) & 1) * 8 + (lane & 7));
    const uint32_t b_cb  = (uint32_t)(((lane >> 3) & 1) * 16);

    for (int s = 0; s < nst; ++s) {
        if (s < nst - 1) asm volatile("cp.async.wait_group 1;" ::: "memory");
        else             asm volatile("cp.async.wait_group 0;" ::: "memory");
        __syncthreads();

        const uint32_t stg = sb + (uint32_t)(s % NSTAGE) * STAGE_B;

        #pragma unroll
        for (int q = 0; q < 2; ++q) {
            const uint32_t sAhi = stg + (uint32_t)q * SLICE_B;
            const uint32_t sAlo = sAhi + 4096;
            const uint32_t sBhi = sAhi + 8192;
            const uint32_t sBlo = sAhi + 12288;

            uint32_t bh[4][2], bl[4][2];
            #pragma unroll
            for (int nf2 = 0; nf2 < 2; ++nf2) {
                uint32_t off = sw32((b_row + (uint32_t)nf2 * 16u) * 32u + b_cb);
                uint32_t r[4];
                ldsm4(r, sBhi + off);
                bh[nf2*2][0] = r[0]; bh[nf2*2][1] = r[1];
                bh[nf2*2+1][0] = r[2]; bh[nf2*2+1][1] = r[3];
                ldsm4(r, sBlo + off);
                bl[nf2*2][0] = r[0]; bl[nf2*2][1] = r[1];
                bl[nf2*2+1][0] = r[2]; bl[nf2*2+1][1] = r[3];
            }

            #pragma unroll
            for (int mf = 0; mf < 4; ++mf) {
                uint32_t off = sw32((a_row + (uint32_t)mf * 16u) * 32u + a_cb);
                uint32_t ah[4], al[4];
                ldsm4(ah, sAhi + off);
                ldsm4(al, sAlo + off);
                #pragma unroll
                for (int nf = 0; nf < 4; ++nf) {
                    mma16816(acc[mf][nf], ah, bh[nf]);
                    mma16816(acc[mf][nf], ah, bl[nf]);
                    mma16816(acc[mf][nf], al, bh[nf]);
                }
            }
        }
        if (s + 2 < nst) load_stage((s + 2) % NSTAGE, s + 2);
    }

    const int gid = lane >> 2;
    const int tig = lane & 3;
    #pragma unroll
    for (int mf = 0; mf < 4; ++mf) {
        int row0 = mBase + wmB + mf * 16 + gid;
        #pragma unroll
        for (int nf = 0; nf < 4; ++nf) {
            int col = nBase + wnB + nf * 8 + tig * 2;
            if (col < Nreal) {
                float2 v0 = make_float2(acc[mf][nf][0], acc[mf][nf][1]);
                float2 v1 = make_float2(acc[mf][nf][2], acc[mf][nf][3]);
                *(float2*)(C + (size_t)row0 * Nreal + col) = v0;
                *(float2*)(C + (size_t)(row0 + 8) * Nreal + col) = v1;
            }
        }
    }
}

// ---------------- dt projection + softplus ------------------------------------
__global__ void __launch_bounds__(256)
dt_kernel(const float* __restrict__ W_dt, const float* __restrict__ dt_bias)
{
    __shared__ float s_r[64 * DT_RANK];
    const int t0 = blockIdx.x * 64;
    const int d  = blockIdx.y * 256 + threadIdx.x;

    #pragma unroll
    for (int k = 0; k < 16; ++k) {
        int idx = threadIdx.x + k * 256;
        int row = idx >> 6, col = idx & 63;
        s_r[idx] = g_zx[(size_t)(t0 + row) * D_PROJ + OFF_DT + col];
    }
    __syncthreads();

    float w[DT_RANK];
    #pragma unroll
    for (int k = 0; k < DT_RANK; ++k)
        w[k] = W_dt[(size_t)k * D_INNER + d];

    const float bias2 = 2.f * dt_bias[d];

    for (int tt = 0; tt < 64; ++tt) {
        const float4* rp = (const float4*)(s_r + tt * DT_RANK);
        float s = bias2;
        #pragma unroll
        for (int k4 = 0; k4 < DT_RANK / 4; ++k4) {
            float4 r4 = rp[k4];
            s = fmaf(r4.x, w[k4*4+0], s);
            s = fmaf(r4.y, w[k4*4+1], s);
            s = fmaf(r4.z, w[k4*4+2], s);
            s = fmaf(r4.w, w[k4*4+3], s);
        }
        float sp = (s > 20.f) ? s : log1pf(__expf(s));
        g_delta[(size_t)(t0 + tt) * D_INNER + d] = sp;
    }
}

// ---------------- causal depthwise conv (K=4) + bias + silu -----------------
__global__ void __launch_bounds__(256)
conv_kernel(const float* __restrict__ w, const float* __restrict__ b)
{
    int idx = blockIdx.x * blockDim.x + threadIdx.x;
    if (idx >= L_SEQ * D_XB) return;
    int t = idx >> 9, c = idx & (D_XB - 1);
    float acc = b[c];
    #pragma unroll
    for (int k = 0; k < KCONV; ++k) {
        int tt = t - (KCONV - 1) + k;
        if (tt >= 0)
            acc = fmaf(w[c * KCONV + k], g_zx[(size_t)tt * D_PROJ + OFF_X + c], acc);
    }
    g_xconv[idx] = acc / (1.f + __expf(-acc));
}

// ---------------- chunked selective scan -------------------------------------
__global__ void __launch_bounds__(256)
scan_phase_a(const float* __restrict__ A_log)
{
    const int g   = blockIdx.x;
    const int j   = blockIdx.y;
    const int tid = threadIdx.x;
    const int p   = tid >> 4;
    const int n   = tid & 15;
    const int gx  = g >> 2;
    const int d   = g * D_STATE + p;

    __shared__ float s_dv[CH * 16], s_xv[CH * 16], s_B[CH * 16];

    const int i0 = tid >> 4, l = tid & 15;
    const int tbase = j * CH;
    #pragma unroll
    for (int r = 0; r < CH; r += 16) {
        int t = tbase + i0 + r;
        s_dv[(i0 + r) * 16 + l] = g_delta[(size_t)t * D_INNER + g * 16 + l];
        s_xv[(i0 + r) * 16 + l] = g_xconv[(size_t)t * D_XB + gx * 16 + l];
        s_B [(i0 + r) * 16 + l] = g_zx[(size_t)t * D_PROJ + OFF_B + gx * 16 + l];
    }
    __syncthreads();

    const float A = -expf(A_log[d * D_STATE + n]);
    float h = 0.f, P = 1.f;
    #pragma unroll 8
    for (int i = 0; i < CH; ++i) {
        float dv = s_dv[i * 16 + p];
        float xv = s_xv[i * 16 + p];
        float Bv = s_B [i * 16 + n];
        float a  = __expf(dv * A);
        P *= a;
        h = fmaf(a, h, dv * xv * Bv);
    }
    int idx = (j * G_HEADS + g) * 256 + tid;
    g_P[idx] = P;
    g_E[idx] = h;
}

__global__ void __launch_bounds__(256)
scan_phase_b()
{
    const int g   = blockIdx.x;
    const int tid = threadIdx.x;
    float c = 0.f;
    #pragma unroll
    for (int j = 0; j < NCH; ++j) {
        int idx = (j * G_HEADS + g) * 256 + tid;
        float P = g_P[idx];
        float E = g_E[idx];
        g_Cin[idx] = c;
        c = fmaf(P, c, E);
    }
}

__global__ void __launch_bounds__(256)
scan_phase_c(const float* __restrict__ A_log, const float* __restrict__ Dp)
{
    const int g   = blockIdx.x;
    const int j   = blockIdx.y;
    const int tid = threadIdx.x;
    const int p   = tid >> 4;
    const int n   = tid & 15;
    const int gx  = g >> 2;
    const int d   = g * D_STATE + p;

    __shared__ float s_dv[CH * 16], s_xv[CH * 16], s_B[CH * 16],
                     s_C [CH * 16], s_z [CH * 16];

    const int i0 = tid >> 4, l = tid & 15;
    const int tbase = j * CH;
    #pragma unroll
    for (int r = 0; r < CH; r += 16) {
        int t = tbase + i0 + r;
        s_dv[(i0 + r) * 16 + l] = g_delta[(size_t)t * D_INNER + g * 16 + l];
        s_xv[(i0 + r) * 16 + l] = g_xconv[(size_t)t * D_XB + gx * 16 + l];
        s_B [(i0 + r) * 16 + l] = g_zx[(size_t)t * D_PROJ + OFF_B + gx * 16 + l];
        s_C [(i0 + r) * 16 + l] = g_zx[(size_t)t * D_PROJ + OFF_C + g * 16 + l];
        s_z [(i0 + r) * 16 + l] = g_zx[(size_t)t * D_PROJ + OFF_Z + g * 16 + l];
    }
    __syncthreads();

    const float A  = -expf(A_log[d * D_STATE + n]);
    const float Dv = Dp[d];
    float h = g_Cin[(j * G_HEADS + g) * 256 + tid];

    #pragma unroll 4
    for (int i = 0; i < CH; ++i) {
        float dv = s_dv[i * 16 + p];
        float xv = s_xv[i * 16 + p];
        float Bv = s_B [i * 16 + n];
        float Cv = s_C [i * 16 + n];

        float a = __expf(dv * A);
        h = fmaf(a, h, dv * xv * Bv);

        float part = h * Cv;
        part += __shfl_xor_sync(0xffffffffu, part, 8);
        part += __shfl_xor_sync(0xffffffffu, part, 4);
        part += __shfl_xor_sync(0xffffffffu, part, 2);
        part += __shfl_xor_sync(0xffffffffu, part, 1);

        if (n == 0) {
            float zv = s_z[i * 16 + p];
            float sz = zv / (1.f + __expf(-zv));
            float yv = (part + Dv * xv) * sz;
            size_t oi = (size_t)(tbase + i) * D_INNER + d;
            __nv_bfloat16 hb = __float2bfloat16_rn(yv);
            g_ahi[oi] = hb;
            g_alo[oi] = __float2bfloat16_rn(yv - __bfloat162float(hb));
        }
    }
}

// ---------------- launch ------------------------------------------------------
extern "C" void kernel_launch(void* const* d_in, const int* in_sizes, int n_in,
                              void* d_out, int out_size)
{
    const float* hidden  = (const float*)d_in[0];
    const float* W_in    = (const float*)d_in[1];
    const float* conv_w  = (const float*)d_in[2];
    const float* conv_b  = (const float*)d_in[3];
    const float* W_dt    = (const float*)d_in[4];
    const float* dt_bias = (const float*)d_in[5];
    const float* A_log   = (const float*)d_in[6];
    const float* Dp      = (const float*)d_in[7];
    const float* W_out   = (const float*)d_in[8];
    float*       out     = (float*)d_out;

    cudaFuncSetAttribute(gemm_tc_kernel,
                         cudaFuncAttributeMaxDynamicSharedMemorySize, GEMM_SMEM);

    float* zx;
    __nv_bfloat16 *ahi, *alo, *w1hi, *w1lo, *w2hi, *w2lo;
    cudaGetSymbolAddress((void**)&zx,   g_zx);
    cudaGetSymbolAddress((void**)&ahi,  g_ahi);
    cudaGetSymbolAddress((void**)&alo,  g_alo);
    cudaGetSymbolAddress((void**)&w1hi, g_w1hi);
    cudaGetSymbolAddress((void**)&w1lo, g_w1lo);
    cudaGetSymbolAddress((void**)&w2hi, g_w2hi);
    cudaGetSymbolAddress((void**)&w2lo, g_w2lo);

    // 1-3) operand prep (GEMM1 lands in profiled slot 4)
    transpose_wt<<<dim3(NPAD1 / 32, D_MODEL / 32), 256>>>(W_in, w1hi, w1lo, D_MODEL, D_PROJ);
    transpose_wt<<<dim3(D_MODEL / 32, D_INNER / 32), 256>>>(W_out, w2hi, w2lo, D_INNER, D_MODEL);
    convert_hilo<<<(L_SEQ * D_MODEL) / 1024, 256>>>(hidden, ahi, alo, L_SEQ * D_MODEL);

    // 4) zxbcdt = hidden @ W_in
    gemm_tc_kernel<<<dim3(NPAD1 / 128, L_SEQ / 128), 256, GEMM_SMEM>>>(
        ahi, alo, w1hi, w1lo, zx, D_PROJ, D_MODEL);

    // 5-6) delta + conv
    dt_kernel<<<dim3(L_SEQ / 64, D_INNER / 256), 256>>>(W_dt, dt_bias);
    conv_kernel<<<(L_SEQ * D_XB + 255) / 256, 256>>>(conv_w, conv_b);

    // 7-9) chunked scan (phase C writes bf16 hi/lo yg into g_ahi/g_alo)
    scan_phase_a<<<dim3(G_HEADS, NCH), 256>>>(A_log);
    scan_phase_b<<<G_HEADS, 256>>>();
    scan_phase_c<<<dim3(G_HEADS, NCH), 256>>>(A_log, Dp);

    // 10) out = yg @ W_out
    gemm_tc_kernel<<<dim3(D_MODEL / 128, L_SEQ / 128), 256, GEMM_SMEM>>>(
        ahi, alo, w2hi, w2lo, out, D_MODEL, D_INNER);
}

// round 8
// speedup vs baseline: 1.0454x; 1.0129x over previous
#include <cuda_runtime.h>
#include <cuda_bf16.h>
#include <cstdint>

// ---------------- problem constants ----------------
#define L_SEQ    2048
#define D_MODEL  1024
#define D_INNER  2048
#define D_XB     512
#define D_STATE  16
#define DT_RANK  64
#define KCONV    4
#define G_HEADS  128
#define GX_HEADS 32
#define D_PROJ   5184
#define NPAD1    5248          // D_PROJ padded to multiple of 128

#define OFF_Z    0
#define OFF_X    2048
#define OFF_B    2560
#define OFF_C    3072
#define OFF_DT   5120

// scan chunking
#define CH       64
#define NCH      32            // L_SEQ / CH

// ---------------- scratch (static device globals; no runtime allocation) ----
__device__ float g_zx   [L_SEQ * D_PROJ];
__device__ float g_delta[L_SEQ * D_INNER];
__device__ float g_xconv[L_SEQ * D_XB];

__device__ float g_P  [NCH * G_HEADS * 256];
__device__ float g_E  [NCH * G_HEADS * 256];
__device__ float g_Cin[NCH * G_HEADS * 256];

__device__ __nv_bfloat16 g_ahi [L_SEQ * D_INNER];
__device__ __nv_bfloat16 g_alo [L_SEQ * D_INNER];
__device__ __nv_bfloat16 g_w1hi[NPAD1 * D_MODEL];
__device__ __nv_bfloat16 g_w1lo[NPAD1 * D_MODEL];
__device__ __nv_bfloat16 g_w2hi[D_MODEL * D_INNER];
__device__ __nv_bfloat16 g_w2lo[D_MODEL * D_INNER];

// ================= low-level helpers =========================================
__device__ __forceinline__ uint32_t smem_u32(const void* p) {
    return (uint32_t)__cvta_generic_to_shared(p);
}
__device__ __forceinline__ void cpasync16(uint32_t saddr, const void* g) {
    asm volatile("cp.async.cg.shared.global [%0], [%1], 16;" :: "r"(saddr), "l"(g));
}
__device__ __forceinline__ void ldsm4(uint32_t* r, uint32_t addr) {
    asm volatile("ldmatrix.sync.aligned.m8n8.x4.shared.b16 {%0,%1,%2,%3}, [%4];"
        : "=r"(r[0]), "=r"(r[1]), "=r"(r[2]), "=r"(r[3]) : "r"(addr));
}
__device__ __forceinline__ void mma16816(float* d, const uint32_t* a, const uint32_t* b) {
    asm volatile("mma.sync.aligned.m16n8k16.row.col.f32.bf16.bf16.f32 "
        "{%0,%1,%2,%3}, {%4,%5,%6,%7}, {%8,%9}, {%0,%1,%2,%3};"
        : "+f"(d[0]), "+f"(d[1]), "+f"(d[2]), "+f"(d[3])
        : "r"(a[0]), "r"(a[1]), "r"(a[2]), "r"(a[3]), "r"(b[0]), "r"(b[1]));
}
__device__ __forceinline__ uint32_t sw32(uint32_t off) {
    return off ^ ((off >> 3) & 0x70);
}

// ================= fp32 -> bf16 hi/lo conversion =============================
__global__ void __launch_bounds__(256)
convert_hilo(const float* __restrict__ in, __nv_bfloat16* __restrict__ hi,
             __nv_bfloat16* __restrict__ lo, int count)
{
    int i = (blockIdx.x * 256 + threadIdx.x) * 4;
    if (i >= count) return;
    float4 v = *(const float4*)(in + i);
    float vv[4] = {v.x, v.y, v.z, v.w};
    __nv_bfloat16 h[4], l[4];
    #pragma unroll
    for (int j = 0; j < 4; ++j) {
        h[j] = __float2bfloat16_rn(vv[j]);
        l[j] = __float2bfloat16_rn(vv[j] - __bfloat162float(h[j]));
    }
    *(uint2*)(hi + i) = *(uint2*)h;
    *(uint2*)(lo + i) = *(uint2*)l;
}

// ================= transpose W [K,N] -> [Npad,K] bf16 hi/lo ==================
__global__ void __launch_bounds__(256)
transpose_wt(const float* __restrict__ W, __nv_bfloat16* __restrict__ Thi,
             __nv_bfloat16* __restrict__ Tlo, int K, int N)
{
    __shared__ float tile[32][33];
    int n0 = blockIdx.x * 32;
    int k0 = blockIdx.y * 32;
    int tx = threadIdx.x & 31, ty = threadIdx.x >> 5;
    #pragma unroll
    for (int r = 0; r < 4; ++r) {
        int k = k0 + ty + r * 8;
        int n = n0 + tx;
        tile[ty + r * 8][tx] = (n < N) ? W[(size_t)k * N + n] : 0.f;
    }
    __syncthreads();
    #pragma unroll
    for (int r = 0; r < 4; ++r) {
        int n = n0 + ty + r * 8;
        int k = k0 + tx;
        float v = tile[tx][ty + r * 8];
        __nv_bfloat16 h = __float2bfloat16_rn(v);
        Thi[(size_t)n * K + k] = h;
        Tlo[(size_t)n * K + k] = __float2bfloat16_rn(v - __bfloat162float(h));
    }
}

// ================= split-bf16 warp-MMA GEMM ==================================
// CTA tile (MF*32) x 128, 8 warps (2m x 4n), warp tile (MF*16) x 32.
// Pipeline stage = TWO k=16 slices; 3 stages; product-major MMA ordering.
#define NSTAGE   3

template<int MF>
__global__ void __launch_bounds__(256, 2)
gemm_tc_kernel(const __nv_bfloat16* __restrict__ Ahi, const __nv_bfloat16* __restrict__ Alo,
               const __nv_bfloat16* __restrict__ Bhi, const __nv_bfloat16* __restrict__ Blo,
               float* __restrict__ C, int Nreal, int K)
{
    constexpr int MROWS = MF * 32;                    // CTA M tile
    constexpr int ABYTES = MROWS * 32;                // one A array per k=16 slice
    constexpr int SLICE  = 2 * ABYTES + 8192;         // Ahi|Alo|Bhi|Blo
    constexpr int STAGE  = 2 * SLICE;
    constexpr int ACH    = MROWS * 2;                 // 16B chunks per A array
    constexpr int CPT    = (MROWS * 4 + 512) / 256;   // chunks per thread per slice

    extern __shared__ char sm[];
    const uint32_t sb = smem_u32(sm);
    const int tid   = threadIdx.x;
    const int lane  = tid & 31;
    const int wid   = tid >> 5;
    const int nBase = blockIdx.x * 128;
    const int mBase = blockIdx.y * MROWS;
    const int wmB   = (wid >> 2) * (MF * 16);
    const int wnB   = (wid & 3) * 32;

    const int nst = K >> 5;               // k=32 stages

    float acc[MF][4][4];
    #pragma unroll
    for (int a = 0; a < MF; ++a)
        #pragma unroll
        for (int b = 0; b < 4; ++b)
            #pragma unroll
            for (int c = 0; c < 4; ++c) acc[a][b][c] = 0.f;

    // per-thread load table for one slice
    int lrow[CPT], lch[CPT], larr[CPT];
    uint32_t lsw[CPT];
    #pragma unroll
    for (int i = 0; i < CPT; ++i) {
        int idx = tid + i * 256;
        if (idx < 2 * ACH) {
            larr[i] = idx / ACH;                       // 0 = Ahi, 1 = Alo
            int w = idx % ACH;
            lrow[i] = w >> 1; lch[i] = w & 1;
            lsw[i]  = (uint32_t)larr[i] * ABYTES
                    + sw32((uint32_t)lrow[i] * 32u + (uint32_t)lch[i] * 16u);
        } else {
            int rem = idx - 2 * ACH;
            int bl  = rem >> 8;                        // 0 = Bhi, 1 = Blo
            larr[i] = 2 + bl;
            int w = rem & 255;
            lrow[i] = w >> 1; lch[i] = w & 1;
            lsw[i]  = 2u * ABYTES + (uint32_t)bl * 4096u
                    + sw32((uint32_t)lrow[i] * 32u + (uint32_t)lch[i] * 16u);
        }
    }

    auto load_stage = [&](int stg, int s) {
        uint32_t base = sb + (uint32_t)stg * STAGE;
        #pragma unroll
        for (int q = 0; q < 2; ++q) {
            const size_t koff = (size_t)s * 32 + (size_t)q * 16;
            uint32_t sbase = base + (uint32_t)q * SLICE;
            #pragma unroll
            for (int i = 0; i < CPT; ++i) {
                const __nv_bfloat16* src;
                size_t goff;
                if (larr[i] < 2) {
                    src  = (larr[i] == 0) ? Ahi : Alo;
                    goff = (size_t)(mBase + lrow[i]) * K + koff + (size_t)lch[i] * 8;
                } else {
                    src  = (larr[i] == 2) ? Bhi : Blo;
                    goff = (size_t)(nBase + lrow[i]) * K + koff + (size_t)lch[i] * 8;
                }
                cpasync16(sbase + lsw[i], src + goff);
            }
        }
        asm volatile("cp.async.commit_group;" ::: "memory");
    };

    load_stage(0, 0);
    load_stage(1, 1);

    const uint32_t a_row = (uint32_t)(wmB + (lane & 15));
    const uint32_t a_cb  = (uint32_t)((lane >> 4) * 16);
    const uint32_t b_row = (uint32_t)(wnB + ((lane >> 4) & 1) * 8 + (lane & 7));
    const uint32_t b_cb  = (uint32_t)(((lane >> 3) & 1) * 16);

    for (int s = 0; s < nst; ++s) {
        if (s < nst - 1) asm volatile("cp.async.wait_group 1;" ::: "memory");
        else             asm volatile("cp.async.wait_group 0;" ::: "memory");
        __syncthreads();

        const uint32_t stg = sb + (uint32_t)(s % NSTAGE) * STAGE;

        #pragma unroll
        for (int q = 0; q < 2; ++q) {
            const uint32_t sAhi = stg + (uint32_t)q * SLICE;
            const uint32_t sAlo = sAhi + ABYTES;
            const uint32_t sBhi = sAhi + 2 * ABYTES;
            const uint32_t sBlo = sBhi + 4096;

            // ---- prefetch ALL fragments for this slice ----
            uint32_t bh[4][2], bl[4][2];
            #pragma unroll
            for (int nf2 = 0; nf2 < 2; ++nf2) {
                uint32_t off = sw32((b_row + (uint32_t)nf2 * 16u) * 32u + b_cb);
                uint32_t r[4];
                ldsm4(r, sBhi + off);
                bh[nf2*2][0] = r[0]; bh[nf2*2][1] = r[1];
                bh[nf2*2+1][0] = r[2]; bh[nf2*2+1][1] = r[3];
                ldsm4(r, sBlo + off);
                bl[nf2*2][0] = r[0]; bl[nf2*2][1] = r[1];
                bl[nf2*2+1][0] = r[2]; bl[nf2*2+1][1] = r[3];
            }
            uint32_t ah[MF][4], al[MF][4];
            #pragma unroll
            for (int mf = 0; mf < MF; ++mf) {
                uint32_t off = sw32((a_row + (uint32_t)mf * 16u) * 32u + a_cb);
                ldsm4(ah[mf], sAhi + off);
                ldsm4(al[mf], sAlo + off);
            }

            // ---- product-major MMA: same-acc reuse distance = MF*4 ----
            #pragma unroll
            for (int mf = 0; mf < MF; ++mf)
                #pragma unroll
                for (int nf = 0; nf < 4; ++nf)
                    mma16816(acc[mf][nf], ah[mf], bh[nf]);
            #pragma unroll
            for (int mf = 0; mf < MF; ++mf)
                #pragma unroll
                for (int nf = 0; nf < 4; ++nf)
                    mma16816(acc[mf][nf], ah[mf], bl[nf]);
            #pragma unroll
            for (int mf = 0; mf < MF; ++mf)
                #pragma unroll
                for (int nf = 0; nf < 4; ++nf)
                    mma16816(acc[mf][nf], al[mf], bh[nf]);
        }
        if (s + 2 < nst) load_stage((s + 2) % NSTAGE, s + 2);
    }

    const int gid = lane >> 2;
    const int tig = lane & 3;
    #pragma unroll
    for (int mf = 0; mf < MF; ++mf) {
        int row0 = mBase + wmB + mf * 16 + gid;
        #pragma unroll
        for (int nf = 0; nf < 4; ++nf) {
            int col = nBase + wnB + nf * 8 + tig * 2;
            if (col < Nreal) {
                float2 v0 = make_float2(acc[mf][nf][0], acc[mf][nf][1]);
                float2 v1 = make_float2(acc[mf][nf][2], acc[mf][nf][3]);
                *(float2*)(C + (size_t)row0 * Nreal + col) = v0;
                *(float2*)(C + (size_t)(row0 + 8) * Nreal + col) = v1;
            }
        }
    }
}

// ---------------- dt projection + softplus ------------------------------------
__global__ void __launch_bounds__(256)
dt_kernel(const float* __restrict__ W_dt, const float* __restrict__ dt_bias)
{
    __shared__ float s_r[64 * DT_RANK];
    const int t0 = blockIdx.x * 64;
    const int d  = blockIdx.y * 256 + threadIdx.x;

    #pragma unroll
    for (int k = 0; k < 16; ++k) {
        int idx = threadIdx.x + k * 256;
        int row = idx >> 6, col = idx & 63;
        s_r[idx] = g_zx[(size_t)(t0 + row) * D_PROJ + OFF_DT + col];
    }
    __syncthreads();

    float w[DT_RANK];
    #pragma unroll
    for (int k = 0; k < DT_RANK; ++k)
        w[k] = W_dt[(size_t)k * D_INNER + d];

    const float bias2 = 2.f * dt_bias[d];

    for (int tt = 0; tt < 64; ++tt) {
        const float4* rp = (const float4*)(s_r + tt * DT_RANK);
        float s = bias2;
        #pragma unroll
        for (int k4 = 0; k4 < DT_RANK / 4; ++k4) {
            float4 r4 = rp[k4];
            s = fmaf(r4.x, w[k4*4+0], s);
            s = fmaf(r4.y, w[k4*4+1], s);
            s = fmaf(r4.z, w[k4*4+2], s);
            s = fmaf(r4.w, w[k4*4+3], s);
        }
        float sp = (s > 20.f) ? s : log1pf(__expf(s));
        g_delta[(size_t)(t0 + tt) * D_INNER + d] = sp;
    }
}

// ---------------- causal depthwise conv (K=4) + bias + silu -----------------
__global__ void __launch_bounds__(256)
conv_kernel(const float* __restrict__ w, const float* __restrict__ b)
{
    int idx = blockIdx.x * blockDim.x + threadIdx.x;
    if (idx >= L_SEQ * D_XB) return;
    int t = idx >> 9, c = idx & (D_XB - 1);
    float acc = b[c];
    #pragma unroll
    for (int k = 0; k < KCONV; ++k) {
        int tt = t - (KCONV - 1) + k;
        if (tt >= 0)
            acc = fmaf(w[c * KCONV + k], g_zx[(size_t)tt * D_PROJ + OFF_X + c], acc);
    }
    g_xconv[idx] = acc / (1.f + __expf(-acc));
}

// ---------------- chunked selective scan -------------------------------------
__global__ void __launch_bounds__(256)
scan_phase_a(const float* __restrict__ A_log)
{
    const int g   = blockIdx.x;
    const int j   = blockIdx.y;
    const int tid = threadIdx.x;
    const int p   = tid >> 4;
    const int n   = tid & 15;
    const int gx  = g >> 2;
    const int d   = g * D_STATE + p;

    __shared__ float s_dv[CH * 16], s_xv[CH * 16], s_B[CH * 16];

    const int i0 = tid >> 4, l = tid & 15;
    const int tbase = j * CH;
    #pragma unroll
    for (int r = 0; r < CH; r += 16) {
        int t = tbase + i0 + r;
        s_dv[(i0 + r) * 16 + l] = g_delta[(size_t)t * D_INNER + g * 16 + l];
        s_xv[(i0 + r) * 16 + l] = g_xconv[(size_t)t * D_XB + gx * 16 + l];
        s_B [(i0 + r) * 16 + l] = g_zx[(size_t)t * D_PROJ + OFF_B + gx * 16 + l];
    }
    __syncthreads();

    const float A = -expf(A_log[d * D_STATE + n]);
    float h = 0.f, P = 1.f;
    #pragma unroll 8
    for (int i = 0; i < CH; ++i) {
        float dv = s_dv[i * 16 + p];
        float xv = s_xv[i * 16 + p];
        float Bv = s_B [i * 16 + n];
        float a  = __expf(dv * A);
        P *= a;
        h = fmaf(a, h, dv * xv * Bv);
    }
    int idx = (j * G_HEADS + g) * 256 + tid;
    g_P[idx] = P;
    g_E[idx] = h;
}

__global__ void __launch_bounds__(256)
scan_phase_b()
{
    const int g   = blockIdx.x;
    const int tid = threadIdx.x;
    float c = 0.f;
    #pragma unroll
    for (int j = 0; j < NCH; ++j) {
        int idx = (j * G_HEADS + g) * 256 + tid;
        float P = g_P[idx];
        float E = g_E[idx];
        g_Cin[idx] = c;
        c = fmaf(P, c, E);
    }
}

__global__ void __launch_bounds__(256)
scan_phase_c(const float* __restrict__ A_log, const float* __restrict__ Dp)
{
    const int g   = blockIdx.x;
    const int j   = blockIdx.y;
    const int tid = threadIdx.x;
    const int p   = tid >> 4;
    const int n   = tid & 15;
    const int gx  = g >> 2;
    const int d   = g * D_STATE + p;

    __shared__ float s_dv[CH * 16], s_xv[CH * 16], s_B[CH * 16],
                     s_C [CH * 16], s_z [CH * 16];

    const int i0 = tid >> 4, l = tid & 15;
    const int tbase = j * CH;
    #pragma unroll
    for (int r = 0; r < CH; r += 16) {
        int t = tbase + i0 + r;
        s_dv[(i0 + r) * 16 + l] = g_delta[(size_t)t * D_INNER + g * 16 + l];
        s_xv[(i0 + r) * 16 + l] = g_xconv[(size_t)t * D_XB + gx * 16 + l];
        s_B [(i0 + r) * 16 + l] = g_zx[(size_t)t * D_PROJ + OFF_B + gx * 16 + l];
        s_C [(i0 + r) * 16 + l] = g_zx[(size_t)t * D_PROJ + OFF_C + g * 16 + l];
        s_z [(i0 + r) * 16 + l] = g_zx[(size_t)t * D_PROJ + OFF_Z + g * 16 + l];
    }
    __syncthreads();

    const float A  = -expf(A_log[d * D_STATE + n]);
    const float Dv = Dp[d];
    float h = g_Cin[(j * G_HEADS + g) * 256 + tid];

    #pragma unroll 4
    for (int i = 0; i < CH; ++i) {
        float dv = s_dv[i * 16 + p];
        float xv = s_xv[i * 16 + p];
        float Bv = s_B [i * 16 + n];
        float Cv = s_C [i * 16 + n];

        float a = __expf(dv * A);
        h = fmaf(a, h, dv * xv * Bv);

        float part = h * Cv;
        part += __shfl_xor_sync(0xffffffffu, part, 8);
        part += __shfl_xor_sync(0xffffffffu, part, 4);
        part += __shfl_xor_sync(0xffffffffu, part, 2);
        part += __shfl_xor_sync(0xffffffffu, part, 1);

        if (n == 0) {
            float zv = s_z[i * 16 + p];
            float sz = zv / (1.f + __expf(-zv));
            float yv = (part + Dv * xv) * sz;
            size_t oi = (size_t)(tbase + i) * D_INNER + d;
            __nv_bfloat16 hb = __float2bfloat16_rn(yv);
            g_ahi[oi] = hb;
            g_alo[oi] = __float2bfloat16_rn(yv - __bfloat162float(hb));
        }
    }
}

// ---------------- launch ------------------------------------------------------
extern "C" void kernel_launch(void* const* d_in, const int* in_sizes, int n_in,
                              void* d_out, int out_size)
{
    const float* hidden  = (const float*)d_in[0];
    const float* W_in    = (const float*)d_in[1];
    const float* conv_w  = (const float*)d_in[2];
    const float* conv_b  = (const float*)d_in[3];
    const float* W_dt    = (const float*)d_in[4];
    const float* dt_bias = (const float*)d_in[5];
    const float* A_log   = (const float*)d_in[6];
    const float* Dp      = (const float*)d_in[7];
    const float* W_out   = (const float*)d_in[8];
    float*       out     = (float*)d_out;

    const int SMEM1 = NSTAGE * 2 * (128 * 64 + 8192);  // MF=4: 96KB
    const int SMEM2 = NSTAGE * 2 * (64 * 64 + 8192);   // MF=2: 72KB
    cudaFuncSetAttribute(gemm_tc_kernel<4>,
                         cudaFuncAttributeMaxDynamicSharedMemorySize, SMEM1);
    cudaFuncSetAttribute(gemm_tc_kernel<2>,
                         cudaFuncAttributeMaxDynamicSharedMemorySize, SMEM2);

    float* zx;
    __nv_bfloat16 *ahi, *alo, *w1hi, *w1lo, *w2hi, *w2lo;
    cudaGetSymbolAddress((void**)&zx,   g_zx);
    cudaGetSymbolAddress((void**)&ahi,  g_ahi);
    cudaGetSymbolAddress((void**)&alo,  g_alo);
    cudaGetSymbolAddress((void**)&w1hi, g_w1hi);
    cudaGetSymbolAddress((void**)&w1lo, g_w1lo);
    cudaGetSymbolAddress((void**)&w2hi, g_w2hi);
    cudaGetSymbolAddress((void**)&w2lo, g_w2lo);

    // 1-3) operand prep (GEMM1 lands in profiled slot 4)
    transpose_wt<<<dim3(NPAD1 / 32, D_MODEL / 32), 256>>>(W_in, w1hi, w1lo, D_MODEL, D_PROJ);
    transpose_wt<<<dim3(D_MODEL / 32, D_INNER / 32), 256>>>(W_out, w2hi, w2lo, D_INNER, D_MODEL);
    convert_hilo<<<(L_SEQ * D_MODEL) / 1024, 256>>>(hidden, ahi, alo, L_SEQ * D_MODEL);

    // 4) zxbcdt = hidden @ W_in  (128x128 tiles)
    gemm_tc_kernel<4><<<dim3(NPAD1 / 128, L_SEQ / 128), 256, SMEM1>>>(
        ahi, alo, w1hi, w1lo, zx, D_PROJ, D_MODEL);

    // 5-6) delta + conv
    dt_kernel<<<dim3(L_SEQ / 64, D_INNER / 256), 256>>>(W_dt, dt_bias);
    conv_kernel<<<(L_SEQ * D_XB + 255) / 256, 256>>>(conv_w, conv_b);

    // 7-9) chunked scan (phase C writes bf16 hi/lo yg into g_ahi/g_alo)
    scan_phase_a<<<dim3(G_HEADS, NCH), 256>>>(A_log);
    scan_phase_b<<<G_HEADS, 256>>>();
    scan_phase_c<<<dim3(G_HEADS, NCH), 256>>>(A_log, Dp);

    // 10) out = yg @ W_out  (64x128 tiles -> 256 CTAs, all resident)
    gemm_tc_kernel<2><<<dim3(D_MODEL / 128, L_SEQ / 64), 256, SMEM2>>>(
        ahi, alo, w2hi, w2lo, out, D_MODEL, D_INNER);
}

// round 9
// speedup vs baseline: 1.0583x; 1.0123x over previous
#include <cuda_runtime.h>
#include <cuda_bf16.h>
#include <cstdint>

// ---------------- problem constants ----------------
#define L_SEQ    2048
#define D_MODEL  1024
#define D_INNER  2048
#define D_XB     512
#define D_STATE  16
#define DT_RANK  64
#define KCONV    4
#define G_HEADS  128
#define GX_HEADS 32
#define D_PROJ   5184
#define NPAD1    5248          // D_PROJ padded to multiple of 128

#define OFF_Z    0
#define OFF_X    2048
#define OFF_B    2560
#define OFF_C    3072
#define OFF_DT   5120

// scan chunking
#define CH       64
#define NCH      32            // L_SEQ / CH

// ---------------- scratch (static device globals; no runtime allocation) ----
__device__ float g_zx   [L_SEQ * D_PROJ];
__device__ float g_delta[L_SEQ * D_INNER];
__device__ float g_xconv[L_SEQ * D_XB];

__device__ float g_P  [NCH * G_HEADS * 256];
__device__ float g_E  [NCH * G_HEADS * 256];
__device__ float g_Cin[NCH * G_HEADS * 256];

__device__ __nv_bfloat16 g_ahi [L_SEQ * D_INNER];
__device__ __nv_bfloat16 g_alo [L_SEQ * D_INNER];
__device__ __nv_bfloat16 g_w1hi[NPAD1 * D_MODEL];
__device__ __nv_bfloat16 g_w1lo[NPAD1 * D_MODEL];
__device__ __nv_bfloat16 g_w2hi[D_MODEL * D_INNER];
__device__ __nv_bfloat16 g_w2lo[D_MODEL * D_INNER];

// ================= low-level helpers =========================================
__device__ __forceinline__ uint32_t smem_u32(const void* p) {
    return (uint32_t)__cvta_generic_to_shared(p);
}
__device__ __forceinline__ void cpasync16(uint32_t saddr, const void* g) {
    asm volatile("cp.async.cg.shared.global [%0], [%1], 16;" :: "r"(saddr), "l"(g));
}
__device__ __forceinline__ void ldsm4(uint32_t* r, uint32_t addr) {
    asm volatile("ldmatrix.sync.aligned.m8n8.x4.shared.b16 {%0,%1,%2,%3}, [%4];"
        : "=r"(r[0]), "=r"(r[1]), "=r"(r[2]), "=r"(r[3]) : "r"(addr));
}
__device__ __forceinline__ void mma16816(float* d, const uint32_t* a, const uint32_t* b) {
    asm volatile("mma.sync.aligned.m16n8k16.row.col.f32.bf16.bf16.f32 "
        "{%0,%1,%2,%3}, {%4,%5,%6,%7}, {%8,%9}, {%0,%1,%2,%3};"
        : "+f"(d[0]), "+f"(d[1]), "+f"(d[2]), "+f"(d[3])
        : "r"(a[0]), "r"(a[1]), "r"(a[2]), "r"(a[3]), "r"(b[0]), "r"(b[1]));
}
__device__ __forceinline__ uint32_t sw32(uint32_t off) {
    return off ^ ((off >> 3) & 0x70);
}

// ================= fp32 -> bf16 hi/lo conversion =============================
__global__ void __launch_bounds__(256)
convert_hilo(const float* __restrict__ in, __nv_bfloat16* __restrict__ hi,
             __nv_bfloat16* __restrict__ lo, int count)
{
    int i = (blockIdx.x * 256 + threadIdx.x) * 4;
    if (i >= count) return;
    float4 v = *(const float4*)(in + i);
    float vv[4] = {v.x, v.y, v.z, v.w};
    __nv_bfloat16 h[4], l[4];
    #pragma unroll
    for (int j = 0; j < 4; ++j) {
        h[j] = __float2bfloat16_rn(vv[j]);
        l[j] = __float2bfloat16_rn(vv[j] - __bfloat162float(h[j]));
    }
    *(uint2*)(hi + i) = *(uint2*)h;
    *(uint2*)(lo + i) = *(uint2*)l;
}

// ================= transpose W [K,N] -> [Npad,K] bf16 hi/lo ==================
__global__ void __launch_bounds__(256)
transpose_wt(const float* __restrict__ W, __nv_bfloat16* __restrict__ Thi,
             __nv_bfloat16* __restrict__ Tlo, int K, int N)
{
    __shared__ float tile[32][33];
    int n0 = blockIdx.x * 32;
    int k0 = blockIdx.y * 32;
    int tx = threadIdx.x & 31, ty = threadIdx.x >> 5;
    #pragma unroll
    for (int r = 0; r < 4; ++r) {
        int k = k0 + ty + r * 8;
        int n = n0 + tx;
        tile[ty + r * 8][tx] = (n < N) ? W[(size_t)k * N + n] : 0.f;
    }
    __syncthreads();
    #pragma unroll
    for (int r = 0; r < 4; ++r) {
        int n = n0 + ty + r * 8;
        int k = k0 + tx;
        float v = tile[tx][ty + r * 8];
        __nv_bfloat16 h = __float2bfloat16_rn(v);
        Thi[(size_t)n * K + k] = h;
        Tlo[(size_t)n * K + k] = __float2bfloat16_rn(v - __bfloat162float(h));
    }
}

// ================= split-bf16 warp-MMA GEMM ==================================
// CTA tile (MF*32) x 128, 8 warps (2m x 4n), warp tile (MF*16) x 32.
// Pipeline stage = TWO k=16 slices; 3 stages.
// Persistent: worker handles tiles bid, bid+gridDim.x, ... (grid sized so
// resident workers = exactly one wave; 656-tile GEMM1 gets makespan 2).
#define NSTAGE   3

template<int MF>
__global__ void __launch_bounds__(256, 2)
gemm_tc_kernel(const __nv_bfloat16* __restrict__ Ahi, const __nv_bfloat16* __restrict__ Alo,
               const __nv_bfloat16* __restrict__ Bhi, const __nv_bfloat16* __restrict__ Blo,
               float* __restrict__ C, int Nreal, int K, int tilesX, int ntiles)
{
    constexpr int MROWS = MF * 32;                    // CTA M tile
    constexpr int ABYTES = MROWS * 32;                // one A array per k=16 slice
    constexpr int SLICE  = 2 * ABYTES + 8192;         // Ahi|Alo|Bhi|Blo
    constexpr int STAGE  = 2 * SLICE;
    constexpr int ACH    = MROWS * 2;                 // 16B chunks per A array
    constexpr int CPT    = (MROWS * 4 + 512) / 256;   // chunks per thread per slice

    extern __shared__ char sm[];
    const uint32_t sb = smem_u32(sm);
    const int tid   = threadIdx.x;
    const int lane  = tid & 31;
    const int wid   = tid >> 5;
    const int wmB   = (wid >> 2) * (MF * 16);
    const int wnB   = (wid & 3) * 32;

    const int nst = K >> 5;               // k=32 stages

    // per-thread load table for one slice
    int lrow[CPT], lch[CPT], larr[CPT];
    uint32_t lsw[CPT];
    #pragma unroll
    for (int i = 0; i < CPT; ++i) {
        int idx = tid + i * 256;
        if (idx < 2 * ACH) {
            larr[i] = idx / ACH;                       // 0 = Ahi, 1 = Alo
            int w = idx % ACH;
            lrow[i] = w >> 1; lch[i] = w & 1;
            lsw[i]  = (uint32_t)larr[i] * ABYTES
                    + sw32((uint32_t)lrow[i] * 32u + (uint32_t)lch[i] * 16u);
        } else {
            int rem = idx - 2 * ACH;
            int bl  = rem >> 8;                        // 0 = Bhi, 1 = Blo
            larr[i] = 2 + bl;
            int w = rem & 255;
            lrow[i] = w >> 1; lch[i] = w & 1;
            lsw[i]  = 2u * ABYTES + (uint32_t)bl * 4096u
                    + sw32((uint32_t)lrow[i] * 32u + (uint32_t)lch[i] * 16u);
        }
    }

    const uint32_t a_row = (uint32_t)(wmB + (lane & 15));
    const uint32_t a_cb  = (uint32_t)((lane >> 4) * 16);
    const uint32_t b_row = (uint32_t)(wnB + ((lane >> 4) & 1) * 8 + (lane & 7));
    const uint32_t b_cb  = (uint32_t)(((lane >> 3) & 1) * 16);

    for (int tile = blockIdx.x; tile < ntiles; tile += gridDim.x) {
        const int nBase = (tile % tilesX) * 128;
        const int mBase = (tile / tilesX) * MROWS;

        float acc[MF][4][4];
        #pragma unroll
        for (int a = 0; a < MF; ++a)
            #pragma unroll
            for (int b = 0; b < 4; ++b)
                #pragma unroll
                for (int c = 0; c < 4; ++c) acc[a][b][c] = 0.f;

        auto load_stage = [&](int stg, int s) {
            uint32_t base = sb + (uint32_t)stg * STAGE;
            #pragma unroll
            for (int q = 0; q < 2; ++q) {
                const size_t koff = (size_t)s * 32 + (size_t)q * 16;
                uint32_t sbase = base + (uint32_t)q * SLICE;
                #pragma unroll
                for (int i = 0; i < CPT; ++i) {
                    const __nv_bfloat16* src;
                    size_t goff;
                    if (larr[i] < 2) {
                        src  = (larr[i] == 0) ? Ahi : Alo;
                        goff = (size_t)(mBase + lrow[i]) * K + koff + (size_t)lch[i] * 8;
                    } else {
                        src  = (larr[i] == 2) ? Bhi : Blo;
                        goff = (size_t)(nBase + lrow[i]) * K + koff + (size_t)lch[i] * 8;
                    }
                    cpasync16(sbase + lsw[i], src + goff);
                }
            }
            asm volatile("cp.async.commit_group;" ::: "memory");
        };

        load_stage(0, 0);
        load_stage(1, 1);

        for (int s = 0; s < nst; ++s) {
            if (s < nst - 1) asm volatile("cp.async.wait_group 1;" ::: "memory");
            else             asm volatile("cp.async.wait_group 0;" ::: "memory");
            __syncthreads();

            const uint32_t stg = sb + (uint32_t)(s % NSTAGE) * STAGE;

            #pragma unroll
            for (int q = 0; q < 2; ++q) {
                const uint32_t sAhi = stg + (uint32_t)q * SLICE;
                const uint32_t sAlo = sAhi + ABYTES;
                const uint32_t sBhi = sAhi + 2 * ABYTES;
                const uint32_t sBlo = sBhi + 4096;

                uint32_t bh[4][2], bl[4][2];
                #pragma unroll
                for (int nf2 = 0; nf2 < 2; ++nf2) {
                    uint32_t off = sw32((b_row + (uint32_t)nf2 * 16u) * 32u + b_cb);
                    uint32_t r[4];
                    ldsm4(r, sBhi + off);
                    bh[nf2*2][0] = r[0]; bh[nf2*2][1] = r[1];
                    bh[nf2*2+1][0] = r[2]; bh[nf2*2+1][1] = r[3];
                    ldsm4(r, sBlo + off);
                    bl[nf2*2][0] = r[0]; bl[nf2*2][1] = r[1];
                    bl[nf2*2+1][0] = r[2]; bl[nf2*2+1][1] = r[3];
                }
                uint32_t ah[MF][4], al[MF][4];
                #pragma unroll
                for (int mf = 0; mf < MF; ++mf) {
                    uint32_t off = sw32((a_row + (uint32_t)mf * 16u) * 32u + a_cb);
                    ldsm4(ah[mf], sAhi + off);
                    ldsm4(al[mf], sAlo + off);
                }

                #pragma unroll
                for (int mf = 0; mf < MF; ++mf)
                    #pragma unroll
                    for (int nf = 0; nf < 4; ++nf)
                        mma16816(acc[mf][nf], ah[mf], bh[nf]);
                #pragma unroll
                for (int mf = 0; mf < MF; ++mf)
                    #pragma unroll
                    for (int nf = 0; nf < 4; ++nf)
                        mma16816(acc[mf][nf], ah[mf], bl[nf]);
                #pragma unroll
                for (int mf = 0; mf < MF; ++mf)
                    #pragma unroll
                    for (int nf = 0; nf < 4; ++nf)
                        mma16816(acc[mf][nf], al[mf], bh[nf]);
            }
            if (s + 2 < nst) load_stage((s + 2) % NSTAGE, s + 2);
        }

        const int gid = lane >> 2;
        const int tig = lane & 3;
        #pragma unroll
        for (int mf = 0; mf < MF; ++mf) {
            int row0 = mBase + wmB + mf * 16 + gid;
            #pragma unroll
            for (int nf = 0; nf < 4; ++nf) {
                int col = nBase + wnB + nf * 8 + tig * 2;
                if (col < Nreal) {
                    float2 v0 = make_float2(acc[mf][nf][0], acc[mf][nf][1]);
                    float2 v1 = make_float2(acc[mf][nf][2], acc[mf][nf][3]);
                    *(float2*)(C + (size_t)row0 * Nreal + col) = v0;
                    *(float2*)(C + (size_t)(row0 + 8) * Nreal + col) = v1;
                }
            }
        }
        __syncthreads();   // smem safe before next tile's prologue
    }
}

// ---------------- dt projection + softplus ------------------------------------
__global__ void __launch_bounds__(256)
dt_kernel(const float* __restrict__ W_dt, const float* __restrict__ dt_bias)
{
    __shared__ float s_r[64 * DT_RANK];
    const int t0 = blockIdx.x * 64;
    const int d  = blockIdx.y * 256 + threadIdx.x;

    #pragma unroll
    for (int k = 0; k < 16; ++k) {
        int idx = threadIdx.x + k * 256;
        int row = idx >> 6, col = idx & 63;
        s_r[idx] = g_zx[(size_t)(t0 + row) * D_PROJ + OFF_DT + col];
    }
    __syncthreads();

    float w[DT_RANK];
    #pragma unroll
    for (int k = 0; k < DT_RANK; ++k)
        w[k] = W_dt[(size_t)k * D_INNER + d];

    const float bias2 = 2.f * dt_bias[d];

    for (int tt = 0; tt < 64; ++tt) {
        const float4* rp = (const float4*)(s_r + tt * DT_RANK);
        float s = bias2;
        #pragma unroll
        for (int k4 = 0; k4 < DT_RANK / 4; ++k4) {
            float4 r4 = rp[k4];
            s = fmaf(r4.x, w[k4*4+0], s);
            s = fmaf(r4.y, w[k4*4+1], s);
            s = fmaf(r4.z, w[k4*4+2], s);
            s = fmaf(r4.w, w[k4*4+3], s);
        }
        float sp = (s > 20.f) ? s : log1pf(__expf(s));
        g_delta[(size_t)(t0 + tt) * D_INNER + d] = sp;
    }
}

// ---------------- causal depthwise conv (K=4) + bias + silu -----------------
__global__ void __launch_bounds__(256)
conv_kernel(const float* __restrict__ w, const float* __restrict__ b)
{
    int idx = blockIdx.x * blockDim.x + threadIdx.x;
    if (idx >= L_SEQ * D_XB) return;
    int t = idx >> 9, c = idx & (D_XB - 1);
    float acc = b[c];
    #pragma unroll
    for (int k = 0; k < KCONV; ++k) {
        int tt = t - (KCONV - 1) + k;
        if (tt >= 0)
            acc = fmaf(w[c * KCONV + k], g_zx[(size_t)tt * D_PROJ + OFF_X + c], acc);
    }
    g_xconv[idx] = acc / (1.f + __expf(-acc));
}

// ---------------- chunked selective scan -------------------------------------
__global__ void __launch_bounds__(256)
scan_phase_a(const float* __restrict__ A_log)
{
    const int g   = blockIdx.x;
    const int j   = blockIdx.y;
    const int tid = threadIdx.x;
    const int p   = tid >> 4;
    const int n   = tid & 15;
    const int gx  = g >> 2;
    const int d   = g * D_STATE + p;

    __shared__ float s_dv[CH * 16], s_xv[CH * 16], s_B[CH * 16];

    const int i0 = tid >> 4, l = tid & 15;
    const int tbase = j * CH;
    #pragma unroll
    for (int r = 0; r < CH; r += 16) {
        int t = tbase + i0 + r;
        s_dv[(i0 + r) * 16 + l] = g_delta[(size_t)t * D_INNER + g * 16 + l];
        s_xv[(i0 + r) * 16 + l] = g_xconv[(size_t)t * D_XB + gx * 16 + l];
        s_B [(i0 + r) * 16 + l] = g_zx[(size_t)t * D_PROJ + OFF_B + gx * 16 + l];
    }
    __syncthreads();

    const float A = -expf(A_log[d * D_STATE + n]);
    float h = 0.f, P = 1.f;
    #pragma unroll 8
    for (int i = 0; i < CH; ++i) {
        float dv = s_dv[i * 16 + p];
        float xv = s_xv[i * 16 + p];
        float Bv = s_B [i * 16 + n];
        float a  = __expf(dv * A);
        P *= a;
        h = fmaf(a, h, dv * xv * Bv);
    }
    int idx = (j * G_HEADS + g) * 256 + tid;
    g_P[idx] = P;
    g_E[idx] = h;
}

__global__ void __launch_bounds__(256)
scan_phase_b()
{
    const int g   = blockIdx.x;
    const int tid = threadIdx.x;
    float c = 0.f;
    #pragma unroll
    for (int j = 0; j < NCH; ++j) {
        int idx = (j * G_HEADS + g) * 256 + tid;
        float P = g_P[idx];
        float E = g_E[idx];
        g_Cin[idx] = c;
        c = fmaf(P, c, E);
    }
}

__global__ void __launch_bounds__(256)
scan_phase_c(const float* __restrict__ A_log, const float* __restrict__ Dp)
{
    const int g   = blockIdx.x;
    const int j   = blockIdx.y;
    const int tid = threadIdx.x;
    const int p   = tid >> 4;
    const int n   = tid & 15;
    const int gx  = g >> 2;
    const int d   = g * D_STATE + p;

    __shared__ float s_dv[CH * 16], s_xv[CH * 16], s_B[CH * 16],
                     s_C [CH * 16], s_z [CH * 16];

    const int i0 = tid >> 4, l = tid & 15;
    const int tbase = j * CH;
    #pragma unroll
    for (int r = 0; r < CH; r += 16) {
        int t = tbase + i0 + r;
        s_dv[(i0 + r) * 16 + l] = g_delta[(size_t)t * D_INNER + g * 16 + l];
        s_xv[(i0 + r) * 16 + l] = g_xconv[(size_t)t * D_XB + gx * 16 + l];
        s_B [(i0 + r) * 16 + l] = g_zx[(size_t)t * D_PROJ + OFF_B + gx * 16 + l];
        s_C [(i0 + r) * 16 + l] = g_zx[(size_t)t * D_PROJ + OFF_C + g * 16 + l];
        s_z [(i0 + r) * 16 + l] = g_zx[(size_t)t * D_PROJ + OFF_Z + g * 16 + l];
    }
    __syncthreads();

    const float A  = -expf(A_log[d * D_STATE + n]);
    const float Dv = Dp[d];
    float h = g_Cin[(j * G_HEADS + g) * 256 + tid];

    #pragma unroll 4
    for (int i = 0; i < CH; ++i) {
        float dv = s_dv[i * 16 + p];
        float xv = s_xv[i * 16 + p];
        float Bv = s_B [i * 16 + n];
        float Cv = s_C [i * 16 + n];

        float a = __expf(dv * A);
        h = fmaf(a, h, dv * xv * Bv);

        float part = h * Cv;
        part += __shfl_xor_sync(0xffffffffu, part, 8);
        part += __shfl_xor_sync(0xffffffffu, part, 4);
        part += __shfl_xor_sync(0xffffffffu, part, 2);
        part += __shfl_xor_sync(0xffffffffu, part, 1);

        if (n == 0) {
            float zv = s_z[i * 16 + p];
            float sz = zv / (1.f + __expf(-zv));
            float yv = (part + Dv * xv) * sz;
            size_t oi = (size_t)(tbase + i) * D_INNER + d;
            __nv_bfloat16 hb = __float2bfloat16_rn(yv);
            g_ahi[oi] = hb;
            g_alo[oi] = __float2bfloat16_rn(yv - __bfloat162float(hb));
        }
    }
}

// ---------------- launch ------------------------------------------------------
extern "C" void kernel_launch(void* const* d_in, const int* in_sizes, int n_in,
                              void* d_out, int out_size)
{
    const float* hidden  = (const float*)d_in[0];
    const float* W_in    = (const float*)d_in[1];
    const float* conv_w  = (const float*)d_in[2];
    const float* conv_b  = (const float*)d_in[3];
    const float* W_dt    = (const float*)d_in[4];
    const float* dt_bias = (const float*)d_in[5];
    const float* A_log   = (const float*)d_in[6];
    const float* Dp      = (const float*)d_in[7];
    const float* W_out   = (const float*)d_in[8];
    float*       out     = (float*)d_out;

    const int SMEM1 = NSTAGE * 2 * (128 * 64 + 8192);  // MF=4: 96KB
    const int SMEM2 = NSTAGE * 2 * (64 * 64 + 8192);   // MF=2: 72KB
    cudaFuncSetAttribute(gemm_tc_kernel<4>,
                         cudaFuncAttributeMaxDynamicSharedMemorySize, SMEM1);
    cudaFuncSetAttribute(gemm_tc_kernel<2>,
                         cudaFuncAttributeMaxDynamicSharedMemorySize, SMEM2);

    float* zx;
    __nv_bfloat16 *ahi, *alo, *w1hi, *w1lo, *w2hi, *w2lo;
    cudaGetSymbolAddress((void**)&zx,   g_zx);
    cudaGetSymbolAddress((void**)&ahi,  g_ahi);
    cudaGetSymbolAddress((void**)&alo,  g_alo);
    cudaGetSymbolAddress((void**)&w1hi, g_w1hi);
    cudaGetSymbolAddress((void**)&w1lo, g_w1lo);
    cudaGetSymbolAddress((void**)&w2hi, g_w2hi);
    cudaGetSymbolAddress((void**)&w2lo, g_w2lo);

    // 1-3) operand prep (GEMM1 lands in profiled slot 4)
    transpose_wt<<<dim3(NPAD1 / 32, D_MODEL / 32), 256>>>(W_in, w1hi, w1lo, D_MODEL, D_PROJ);
    transpose_wt<<<dim3(D_MODEL / 32, D_INNER / 32), 256>>>(W_out, w2hi, w2lo, D_INNER, D_MODEL);
    convert_hilo<<<(L_SEQ * D_MODEL) / 1024, 256>>>(hidden, ahi, alo, L_SEQ * D_MODEL);

    // 4) zxbcdt = hidden @ W_in — 592 persistent workers (= resident capacity)
    {
        int tilesX = NPAD1 / 128;                       // 41
        int ntiles = tilesX * (L_SEQ / 128);            // 656
        gemm_tc_kernel<4><<<592, 256, SMEM1>>>(
            ahi, alo, w1hi, w1lo, zx, D_PROJ, D_MODEL, tilesX, ntiles);
    }

    // 5-6) delta + conv
    dt_kernel<<<dim3(L_SEQ / 64, D_INNER / 256), 256>>>(W_dt, dt_bias);
    conv_kernel<<<(L_SEQ * D_XB + 255) / 256, 256>>>(conv_w, conv_b);

    // 7-9) chunked scan (phase C writes bf16 hi/lo yg into g_ahi/g_alo)
    scan_phase_a<<<dim3(G_HEADS, NCH), 256>>>(A_log);
    scan_phase_b<<<G_HEADS, 256>>>();
    scan_phase_c<<<dim3(G_HEADS, NCH), 256>>>(A_log, Dp);

    // 10) out = yg @ W_out — 64x128 tiles, 256 CTAs, single wave
    {
        int tilesX = D_MODEL / 128;                     // 8
        int ntiles = tilesX * (L_SEQ / 64);             // 256
        gemm_tc_kernel<2><<<256, 256, SMEM2>>>(
            ahi, alo, w2hi, w2lo, out, D_MODEL, D_INNER, tilesX, ntiles);
    }
}